// round 11
// baseline (speedup 1.0000x reference)
#include <cuda_runtime.h>
#include <cuda_bf16.h>
#include <cstdint>

typedef unsigned int u32;
typedef unsigned long long u64;

#define THREADS 256
#define POS_TOT 21824
#define ANCH_TOT 196416LL
#define STG 98304   // bytes per pipeline stage (Ahi 16K | Alo 16K | Bhi 32K | Blo 32K)

// ---------------- device scratch (no allocs) ----------------
__device__ __align__(256) __nv_bfloat16 g_fHi[11173888], g_fLo[11173888];
__device__ __align__(256) __nv_bfloat16 g_aHiA[2][11173888], g_aLoA[2][11173888];
__device__ __align__(256) __nv_bfloat16 g_aHiB[2][11173888], g_aLoB[2][11173888];
__device__ __align__(256) __nv_bfloat16 g_wHi[6688512], g_wLo[6688512];

// ---------------- helpers ----------------
__device__ __forceinline__ u32 smem_u32(const void* p) {
    u32 a; asm("{ .reg .u64 t; cvta.to.shared.u64 t, %1; cvt.u32.u64 %0, t; }" : "=r"(a) : "l"(p));
    return a;
}
__device__ __forceinline__ void cp16(u32 saddr, const void* g, bool pred) {
    int sz = pred ? 16 : 0;
    asm volatile("cp.async.cg.shared.global [%0], [%1], 16, %2;"
                 :: "r"(saddr), "l"(g), "r"(sz) : "memory");
}
__device__ __forceinline__ u32 swz(u32 off) { return off ^ ((off >> 3) & 0x70); }

__device__ __forceinline__ void ldm4(u32* r, u32 addr) {
    asm volatile("ldmatrix.sync.aligned.m8n8.x4.shared.b16 {%0,%1,%2,%3}, [%4];"
                 : "=r"(r[0]), "=r"(r[1]), "=r"(r[2]), "=r"(r[3]) : "r"(addr) : "memory");
}
__device__ __forceinline__ void mma16816(float* c, const u32* a, const u32* b) {
    asm volatile(
        "mma.sync.aligned.m16n8k16.row.col.f32.bf16.bf16.f32 "
        "{%0,%1,%2,%3}, {%4,%5,%6,%7}, {%8,%9}, {%0,%1,%2,%3};"
        : "+f"(c[0]), "+f"(c[1]), "+f"(c[2]), "+f"(c[3])
        : "r"(a[0]), "r"(a[1]), "r"(a[2]), "r"(a[3]), "r"(b[0]), "r"(b[1]));
}

// ---------------- prologue: split weights ----------------
// src [Co][256][9] fp32 -> dst [9][Co][256] bf16 hi/lo
__global__ void split_w_k(const float* __restrict__ src, __nv_bfloat16* hi, __nv_bfloat16* lo, int Co) {
    int total = 9 * Co * 256;
    for (int i = blockIdx.x * blockDim.x + threadIdx.x; i < total; i += gridDim.x * blockDim.x) {
        int tap = i / (Co * 256);
        int rem = i - tap * (Co * 256);
        int co = rem >> 8, ci = rem & 255;
        float v = src[(co * 256 + ci) * 9 + tap];
        __nv_bfloat16 h = __float2bfloat16(v);
        __nv_bfloat16 l = __float2bfloat16(v - __bfloat162float(h));
        hi[i] = h; lo[i] = l;
    }
}

// ---------------- prologue: split feats NCHW -> [n][pos][ci] ----------------
__global__ void split_f_k(const float* f0, const float* f1, const float* f2,
                          const float* f3, const float* f4,
                          __nv_bfloat16* hi, __nv_bfloat16* lo) {
    const int pb[6] = {0, 16384, 20480, 21504, 21760, 21824};
    const int Hs[5] = {128, 64, 32, 16, 8};
    const float* fp[5] = {f0, f1, f2, f3, f4};
    long long total = 2LL * POS_TOT * 256;
    for (long long i = (long long)blockIdx.x * blockDim.x + threadIdx.x; i < total;
         i += (long long)gridDim.x * blockDim.x) {
        int n = (int)(i / (POS_TOT * 256LL));
        int r = (int)(i - (long long)n * POS_TOT * 256);
        int pos = r >> 8, ci = r & 255;
        int s = 0;
        for (int k = 1; k < 5; k++) if (pos >= pb[k]) s = k;
        int p = pos - pb[s];
        int HW = Hs[s] * Hs[s];
        float v = fp[s][((long long)n * 256 + ci) * HW + p];
        __nv_bfloat16 h = __float2bfloat16(v);
        __nv_bfloat16 l = __float2bfloat16(v - __bfloat162float(h));
        hi[i] = h; lo[i] = l;
    }
}

// ---------------- main tensor-core conv (warp mma.sync) ----------------
struct CArgs {
    const __nv_bfloat16 *aHi[2], *aLo[2];   // per-head act planes (base, n=0)
    const __nv_bfloat16 *wHi[2], *wLo[2];   // per-head weight region [tap][co][ci]
    const float* bias[2];
    __nv_bfloat16 *oHi[2], *oLo[2];         // MAIN output planes
    float* outP;                            // OUT output
    int cOut, kk;
};

// Block: M=128 pos (8x16 spatial tile) x N=256 co. 8 warps (2m x 4n), each 64M x 64N.
// 36 stages (9 taps x 4 ci-chunks of 64), 96KB/stage double buffered (192KB smem).
template<int MAIN>
__global__ __launch_bounds__(THREADS, 1) void conv_tc(CArgs A)
{
    extern __shared__ __align__(16) char dsm_raw[];

    const int tid = threadIdx.x, wid = tid >> 5, lane = tid & 31;

    const int Hs[5]  = {128, 64, 32, 16, 8};
    const int tXs[5] = {8, 4, 2, 1, 1};
    const int tSt[5] = {0, 128, 160, 168, 170};
    const int posG[5] = {0, 16384, 20480, 21504, 21760};
    const long long posO9[5] = {0, 147456, 184320, 193536, 195840};

    int bt = blockIdx.x;
    int s = 0;
#pragma unroll
    for (int i = 1; i < 5; i++) if (bt >= tSt[i]) s = i;
    int local = bt - tSt[s];
    int H = Hs[s], W = H, tX = tXs[s];
    int y0 = (local / tX) * 8, x0 = (local % tX) * 16;
    int cb = blockIdx.y;
    int z  = blockIdx.z;
    int head = MAIN ? (z >> 1) : 0;
    int n    = MAIN ? (z & 1)  : z;

    const __nv_bfloat16* aHi = A.aHi[head];
    const __nv_bfloat16* aLo = A.aLo[head];
    const __nv_bfloat16* wHi = A.wHi[head];
    const __nv_bfloat16* wLo = A.wLo[head];

    u32 smem0 = (smem_u32(dsm_raw) + 1023u) & ~1023u;
    long long posBaseG = (long long)n * POS_TOT + posG[s];

    // A staging: thread pair per pos-row; each thread 4 chunks of 16B
    const int aRow = tid >> 1;               // 0..127
    const int aC16 = (tid & 1) * 4;          // +q (0..3)
    const int aPr = aRow >> 4, aPc = aRow & 15;
    // B staging: one co-row (128B = 8 chunks) per thread
    const int coB = cb * 256 + tid;
    const bool okB = coB < A.cOut;

    auto issue = [&](int it) {
        int buf = it & 1;
        int tap = it >> 2, kcq = it & 3;
        int dy = tap / 3 - 1, dx = tap % 3 - 1;
        int cic = kcq * 64;
        u32 base = smem0 + buf * STG;
        int gy = y0 + aPr + dy, gx = x0 + aPc + dx;
        bool okA = ((unsigned)gy < (unsigned)H) && ((unsigned)gx < (unsigned)W);
        long long eA = (posBaseG + (long long)gy * W + gx) * 256 + cic;
#pragma unroll
        for (int q = 0; q < 4; q++) {
            u32 so = swz((u32)(aRow * 128 + (aC16 + q) * 16));
            cp16(base + so,         aHi + eA + (aC16 + q) * 8, okA);
            cp16(base + 16384 + so, aLo + eA + (aC16 + q) * 8, okA);
        }
        long long eB = ((long long)tap * A.cOut + coB) * 256 + cic;
#pragma unroll
        for (int q = 0; q < 8; q++) {
            u32 so = swz((u32)(tid * 128 + q * 16));
            cp16(base + 32768 + so, wHi + eB + q * 8, okB);
            cp16(base + 65536 + so, wLo + eB + q * 8, okB);
        }
        asm volatile("cp.async.commit_group;" ::: "memory");
    };

    // warp tile: 64M x 64N
    const int mBase = (wid & 1) * 64;
    const int nBase = (wid >> 1) * 64;
    // ldmatrix lane-derived offsets
    const int aTile  = lane >> 3;
    const int aRowOf = ((aTile & 1) << 3) + (lane & 7);
    const int aKg    = aTile >> 1;
    const int bRowOf = (((lane >> 4) & 1) << 3) + (lane & 7);
    const int bKg    = (lane >> 3) & 1;

    float acc[4][8][4];
#pragma unroll
    for (int mt = 0; mt < 4; mt++)
#pragma unroll
        for (int nt = 0; nt < 8; nt++)
#pragma unroll
            for (int j = 0; j < 4; j++) acc[mt][nt][j] = 0.f;

    issue(0);

    for (int it = 0; it < 36; ++it) {
        if (it < 35) {
            issue(it + 1);
            asm volatile("cp.async.wait_group 1;" ::: "memory");
        } else {
            asm volatile("cp.async.wait_group 0;" ::: "memory");
        }
        __syncthreads();

        u32 base = smem0 + (it & 1) * STG;
#pragma unroll
        for (int k16 = 0; k16 < 4; k16++) {
            int kg0 = k16 * 2;
            u32 ah[4][4], al[4][4];
#pragma unroll
            for (int mt = 0; mt < 4; mt++) {
                u32 off = swz((u32)((mBase + mt * 16 + aRowOf) * 128 + (kg0 + aKg) * 16));
                ldm4(ah[mt], base + off);
                ldm4(al[mt], base + 16384 + off);
            }
#pragma unroll
            for (int nt = 0; nt < 4; nt++) {
                u32 off = swz((u32)((nBase + nt * 16 + bRowOf) * 128 + (kg0 + bKg) * 16));
                u32 bh[4], bl[4];
                ldm4(bh, base + 32768 + off);
                ldm4(bl, base + 65536 + off);
#pragma unroll
                for (int mt = 0; mt < 4; mt++) {
                    mma16816(acc[mt][nt * 2],     ah[mt], &bh[0]);
                    mma16816(acc[mt][nt * 2],     al[mt], &bh[0]);
                    mma16816(acc[mt][nt * 2],     ah[mt], &bl[0]);
                    mma16816(acc[mt][nt * 2 + 1], ah[mt], &bh[2]);
                    mma16816(acc[mt][nt * 2 + 1], al[mt], &bh[2]);
                    mma16816(acc[mt][nt * 2 + 1], ah[mt], &bl[2]);
                }
            }
        }
        __syncthreads();
    }

    // ---------------- epilogue from register accumulators ----------------
    const float* bb = A.bias[head];
    int rQ = lane >> 2;               // row within m16 (0..7)
    int cQ = (lane & 3) * 2;          // col pair within n8

#pragma unroll
    for (int mt = 0; mt < 4; mt++) {
#pragma unroll
        for (int nt = 0; nt < 8; nt++) {
            int co0 = cb * 256 + nBase + nt * 8 + cQ;
#pragma unroll
            for (int half = 0; half < 2; half++) {
                int row = mBase + mt * 16 + rQ + half * 8;
                int pr = row >> 4, pc = row & 15;
                int y = y0 + pr, x = x0 + pc;
                if (x >= W) continue;
                float v0 = acc[mt][nt][half * 2];
                float v1 = acc[mt][nt][half * 2 + 1];
                if (MAIN) {
                    v0 = fmaxf(v0 + bb[co0], 0.f);
                    v1 = fmaxf(v1 + bb[co0 + 1], 0.f);
                    __nv_bfloat16 h0 = __float2bfloat16(v0);
                    __nv_bfloat16 h1 = __float2bfloat16(v1);
                    __nv_bfloat16 l0 = __float2bfloat16(v0 - __bfloat162float(h0));
                    __nv_bfloat16 l1 = __float2bfloat16(v1 - __bfloat162float(h1));
                    u32 hw = (u32)__bfloat16_as_ushort(h0) | ((u32)__bfloat16_as_ushort(h1) << 16);
                    u32 lw = (u32)__bfloat16_as_ushort(l0) | ((u32)__bfloat16_as_ushort(l1) << 16);
                    long long ob = (posBaseG + (long long)y * W + x) * 256 + co0;
                    *(u32*)(A.oHi[head] + ob) = hw;
                    *(u32*)(A.oLo[head] + ob) = lw;
                } else {
                    long long rowB = (long long)n * ANCH_TOT + posO9[s] + (long long)(y * W + x) * 9;
#pragma unroll
                    for (int e = 0; e < 2; e++) {
                        int co = co0 + e;
                        if (co < A.cOut) {
                            float v = (e ? v1 : v0) + bb[co];
                            int a = co / A.kk, c = co - a * A.kk;
                            A.outP[(rowB + a) * (long long)A.kk + c] = v;
                        }
                    }
                }
            }
        }
    }
}

// ---------------- host ----------------
extern "C" void kernel_launch(void* const* d_in, const int* in_sizes, int n_in,
                              void* d_out, int out_size)
{
    (void)in_sizes; (void)out_size;
    if (n_in < 13) return;

    const float* feat[5];
    for (int i = 0; i < 5; i++) feat[i] = (const float*)d_in[i];
    const float* cls_conv_w = (const float*)d_in[5];
    const float* cls_conv_b = (const float*)d_in[6];
    const float* cls_out_w  = (const float*)d_in[7];
    const float* cls_out_b  = (const float*)d_in[8];
    const float* reg_conv_w = (const float*)d_in[9];
    const float* reg_conv_b = (const float*)d_in[10];
    const float* reg_out_w  = (const float*)d_in[11];
    const float* reg_out_b  = (const float*)d_in[12];

    __nv_bfloat16 *fHi, *fLo, *wHi, *wLo;
    __nv_bfloat16 *aHiA, *aLoA, *aHiB, *aLoB;
    cudaGetSymbolAddress((void**)&fHi, g_fHi);
    cudaGetSymbolAddress((void**)&fLo, g_fLo);
    cudaGetSymbolAddress((void**)&wHi, g_wHi);
    cudaGetSymbolAddress((void**)&wLo, g_wLo);
    cudaGetSymbolAddress((void**)&aHiA, g_aHiA);
    cudaGetSymbolAddress((void**)&aLoA, g_aLoA);
    cudaGetSymbolAddress((void**)&aHiB, g_aHiB);
    cudaGetSymbolAddress((void**)&aLoB, g_aLoB);

    const int SMEM_REQ = 2 * STG + 1024;   // 197632
    cudaFuncSetAttribute(conv_tc<1>, cudaFuncAttributeMaxDynamicSharedMemorySize, SMEM_REQ);
    cudaFuncSetAttribute(conv_tc<0>, cudaFuncAttributeMaxDynamicSharedMemorySize, SMEM_REQ);

    const long long PL = 11173888LL;     // plane elems per head
    const long long WTRUNK = 589824LL;   // 9*256*256

    // prologues
    split_f_k<<<4096, 256>>>(feat[0], feat[1], feat[2], feat[3], feat[4], fHi, fLo);
    for (int l = 0; l < 4; l++) {
        split_w_k<<<1024, 256>>>(cls_conv_w + l * 589824, wHi + l * WTRUNK, wLo + l * WTRUNK, 256);
        split_w_k<<<1024, 256>>>(reg_conv_w + l * 589824, wHi + (4 + l) * WTRUNK, wLo + (4 + l) * WTRUNK, 256);
    }
    split_w_k<<<2048, 256>>>(cls_out_w, wHi + 4718592, wLo + 4718592, 819);
    split_w_k<<<256, 256>>>(reg_out_w, wHi + 6605568, wLo + 6605568, 36);

    // trunk layers (N=256 covered by one cb)
    __nv_bfloat16 *srcHi = fHi, *srcLo = fLo;      // layer0: feats (head-shared)
    bool srcIsFeat = true;
    __nv_bfloat16 *pHi[2] = {aHiA, aHiB}, *pLo[2] = {aLoA, aLoB};
    int dstIdx = 0;
    for (int l = 0; l < 4; l++) {
        CArgs a{};
        for (int h = 0; h < 2; h++) {
            a.aHi[h] = srcIsFeat ? srcHi : srcHi + h * PL;
            a.aLo[h] = srcIsFeat ? srcLo : srcLo + h * PL;
            a.wHi[h] = wHi + (h * 4 + l) * WTRUNK;
            a.wLo[h] = wLo + (h * 4 + l) * WTRUNK;
            a.bias[h] = (h == 0 ? cls_conv_b : reg_conv_b) + l * 256;
            a.oHi[h] = pHi[dstIdx] + h * PL;
            a.oLo[h] = pLo[dstIdx] + h * PL;
        }
        a.cOut = 256; a.kk = 1;
        conv_tc<1><<<dim3(171, 1, 4), THREADS, SMEM_REQ>>>(a);
        srcHi = pHi[dstIdx]; srcLo = pLo[dstIdx];
        srcIsFeat = false;
        dstIdx ^= 1;
    }

    // cls output conv (head0 trunk result): 819 channels -> 4 N-tiles of 256
    {
        CArgs a{};
        a.aHi[0] = srcHi; a.aLo[0] = srcLo;
        a.wHi[0] = wHi + 4718592; a.wLo[0] = wLo + 4718592;
        a.bias[0] = cls_out_b;
        a.outP = (float*)d_out;
        a.cOut = 819; a.kk = 91;
        conv_tc<0><<<dim3(171, 4, 2), THREADS, SMEM_REQ>>>(a);
    }
    // reg output conv (head1 trunk result): 36 channels -> 1 N-tile
    {
        CArgs a{};
        a.aHi[0] = srcHi + PL; a.aLo[0] = srcLo + PL;
        a.wHi[0] = wHi + 6605568; a.wLo[0] = wLo + 6605568;
        a.bias[0] = reg_out_b;
        a.outP = (float*)d_out + 35747712LL;   // 2 * 196416 * 91
        a.cOut = 36; a.kk = 4;
        conv_tc<0><<<dim3(171, 1, 2), THREADS, SMEM_REQ>>>(a);
    }
}

// round 12
// speedup vs baseline: 1.2016x; 1.2016x over previous
#include <cuda_runtime.h>
#include <cuda_bf16.h>
#include <cstdint>

typedef unsigned int u32;
typedef unsigned long long u64;

#define THREADS 256
#define POS_TOT 21824
#define ANCH_TOT 196416LL

// ---------------- device scratch (no allocs) ----------------
__device__ __align__(256) __nv_bfloat16 g_fHi[11173888], g_fLo[11173888];
__device__ __align__(256) __nv_bfloat16 g_aHiA[2][11173888], g_aLoA[2][11173888];
__device__ __align__(256) __nv_bfloat16 g_aHiB[2][11173888], g_aLoB[2][11173888];
__device__ __align__(256) __nv_bfloat16 g_wHi[6688512], g_wLo[6688512];

// ---------------- helpers ----------------
__device__ __forceinline__ u32 smem_u32(const void* p) {
    u32 a; asm("{ .reg .u64 t; cvta.to.shared.u64 t, %1; cvt.u32.u64 %0, t; }" : "=r"(a) : "l"(p));
    return a;
}
__device__ __forceinline__ void cp16(u32 saddr, const void* g, bool pred) {
    int sz = pred ? 16 : 0;
    asm volatile("cp.async.cg.shared.global [%0], [%1], 16, %2;"
                 :: "r"(saddr), "l"(g), "r"(sz) : "memory");
}
__device__ __forceinline__ u32 swz(u32 off) { return off ^ ((off >> 3) & 0x70); }

// volatile (no CSE across buffer reuse) but NO memory clobber: ordering vs
// cp.async is provided by __syncthreads(); this frees ptxas to schedule.
__device__ __forceinline__ void ldm4(u32* r, u32 addr) {
    asm volatile("ldmatrix.sync.aligned.m8n8.x4.shared.b16 {%0,%1,%2,%3}, [%4];"
                 : "=r"(r[0]), "=r"(r[1]), "=r"(r[2]), "=r"(r[3]) : "r"(addr));
}
// NON-volatile: pure register computation, outputs consumed by epilogue.
// Allows ptxas to interleave MMAs with the next k-step's ldmatrix (hide LDS lat).
__device__ __forceinline__ void mma16816(float* c, const u32* a, const u32* b) {
    asm("mma.sync.aligned.m16n8k16.row.col.f32.bf16.bf16.f32 "
        "{%0,%1,%2,%3}, {%4,%5,%6,%7}, {%8,%9}, {%0,%1,%2,%3};"
        : "+f"(c[0]), "+f"(c[1]), "+f"(c[2]), "+f"(c[3])
        : "r"(a[0]), "r"(a[1]), "r"(a[2]), "r"(a[3]), "r"(b[0]), "r"(b[1]));
}

// ---------------- prologue: split ALL weights in one launch ----------------
// (one launch instead of 10 -> ncu's "-s 5" lands on conv_tc)
struct WRegion { const float* src; __nv_bfloat16* hi; __nv_bfloat16* lo; int Co; };
struct WAll { WRegion r[10]; };

__global__ void split_w_all(WAll wa) {
    WRegion rg = wa.r[blockIdx.y];
    int total = 9 * rg.Co * 256;
    for (int i = blockIdx.x * blockDim.x + threadIdx.x; i < total; i += gridDim.x * blockDim.x) {
        int tap = i / (rg.Co * 256);
        int rem = i - tap * (rg.Co * 256);
        int co = rem >> 8, ci = rem & 255;
        float v = rg.src[(co * 256 + ci) * 9 + tap];
        __nv_bfloat16 h = __float2bfloat16(v);
        __nv_bfloat16 l = __float2bfloat16(v - __bfloat162float(h));
        rg.hi[i] = h; rg.lo[i] = l;
    }
}

// ---------------- prologue: split feats NCHW -> [n][pos][ci] ----------------
__global__ void split_f_k(const float* f0, const float* f1, const float* f2,
                          const float* f3, const float* f4,
                          __nv_bfloat16* hi, __nv_bfloat16* lo) {
    const int pb[6] = {0, 16384, 20480, 21504, 21760, 21824};
    const int Hs[5] = {128, 64, 32, 16, 8};
    const float* fp[5] = {f0, f1, f2, f3, f4};
    long long total = 2LL * POS_TOT * 256;
    for (long long i = (long long)blockIdx.x * blockDim.x + threadIdx.x; i < total;
         i += (long long)gridDim.x * blockDim.x) {
        int n = (int)(i / (POS_TOT * 256LL));
        int r = (int)(i - (long long)n * POS_TOT * 256);
        int pos = r >> 8, ci = r & 255;
        int s = 0;
        for (int k = 1; k < 5; k++) if (pos >= pb[k]) s = k;
        int p = pos - pb[s];
        int HW = Hs[s] * Hs[s];
        float v = fp[s][((long long)n * 256 + ci) * HW + p];
        __nv_bfloat16 h = __float2bfloat16(v);
        __nv_bfloat16 l = __float2bfloat16(v - __bfloat162float(h));
        hi[i] = h; lo[i] = l;
    }
}

// ---------------- main tensor-core conv (warp mma.sync) ----------------
struct CArgs {
    const __nv_bfloat16 *aHi[2], *aLo[2];   // per-head act planes (base, n=0)
    const __nv_bfloat16 *wHi[2], *wLo[2];   // per-head weight region [tap][co][ci]
    const float* bias[2];
    __nv_bfloat16 *oHi[2], *oLo[2];         // MAIN output planes
    float* outP;                            // OUT output
    int cOut, kk;
};

// Block: M=128 pos (8x16 spatial tile) x N=128 co. 8 warps, each 32M x 64N.
// 36 stages (9 taps x 4 ci-chunks of 64), 64KB/stage double buffered.
template<int MAIN>
__global__ __launch_bounds__(THREADS, 1) void conv_tc(CArgs A)
{
    extern __shared__ __align__(16) char dsm_raw[];

    const int tid = threadIdx.x, wid = tid >> 5, lane = tid & 31;

    const int Hs[5]  = {128, 64, 32, 16, 8};
    const int tXs[5] = {8, 4, 2, 1, 1};
    const int tSt[5] = {0, 128, 160, 168, 170};
    const int posG[5] = {0, 16384, 20480, 21504, 21760};
    const long long posO9[5] = {0, 147456, 184320, 193536, 195840};

    int bt = blockIdx.x;
    int s = 0;
#pragma unroll
    for (int i = 1; i < 5; i++) if (bt >= tSt[i]) s = i;
    int local = bt - tSt[s];
    int H = Hs[s], W = H, tX = tXs[s];
    int y0 = (local / tX) * 8, x0 = (local % tX) * 16;
    int cb = blockIdx.y;
    int z  = blockIdx.z;
    int head = MAIN ? (z >> 1) : 0;
    int n    = MAIN ? (z & 1)  : z;

    const __nv_bfloat16* aHi = A.aHi[head];
    const __nv_bfloat16* aLo = A.aLo[head];
    const __nv_bfloat16* wHi = A.wHi[head];
    const __nv_bfloat16* wLo = A.wLo[head];

    u32 smem0 = (smem_u32(dsm_raw) + 1023u) & ~1023u;

    long long posBaseG = (long long)n * POS_TOT + posG[s];

    // per-thread staging geometry (4 chunks of 16B per 16KB plane)
    int pr_[4], pc_[4], co_[4], c16e_[4];
    u32 swo_[4];
    bool okB_[4];
#pragma unroll
    for (int q = 0; q < 4; q++) {
        int ch = tid * 4 + q;            // 0..1023
        int row = ch >> 3, c16 = ch & 7;
        pr_[q] = row >> 4; pc_[q] = row & 15;
        c16e_[q] = c16 * 8;
        swo_[q] = swz((u32)(row * 128 + c16 * 16));
        co_[q] = cb * 128 + row;
        okB_[q] = co_[q] < A.cOut;
    }

    auto issue = [&](int it) {
        int buf = it & 1;
        int tap = it >> 2, kcq = it & 3;
        int dy = tap / 3 - 1, dx = tap % 3 - 1;
        int cic = kcq * 64;
        u32 base = smem0 + buf * 65536;
        long long wStageBase = ((long long)tap * A.cOut) * 256 + cic;
#pragma unroll
        for (int q = 0; q < 4; q++) {
            int gy = y0 + pr_[q] + dy, gx = x0 + pc_[q] + dx;
            bool ok = ((unsigned)gy < (unsigned)H) && ((unsigned)gx < (unsigned)W);
            long long e = (posBaseG + (long long)gy * W + gx) * 256 + cic + c16e_[q];
            cp16(base + swo_[q],         aHi + e, ok);
            cp16(base + 16384 + swo_[q], aLo + e, ok);
            long long ew = wStageBase + (long long)co_[q] * 256 + c16e_[q];
            cp16(base + 32768 + swo_[q], wHi + ew, okB_[q]);
            cp16(base + 49152 + swo_[q], wLo + ew, okB_[q]);
        }
        asm volatile("cp.async.commit_group;" ::: "memory");
    };

    // warp tile
    const int mBase = (wid & 3) * 32;
    const int nBase = (wid >> 2) * 64;
    // ldmatrix lane-derived offsets
    const int aTile  = lane >> 3;
    const int aRowOf = ((aTile & 1) << 3) + (lane & 7);
    const int aKg    = aTile >> 1;
    const int bRowOf = (((lane >> 4) & 1) << 3) + (lane & 7);
    const int bKg    = (lane >> 3) & 1;

    float acc[2][8][4];
#pragma unroll
    for (int mt = 0; mt < 2; mt++)
#pragma unroll
        for (int nt = 0; nt < 8; nt++)
#pragma unroll
            for (int j = 0; j < 4; j++) acc[mt][nt][j] = 0.f;

    issue(0);

    for (int it = 0; it < 36; ++it) {
        if (it < 35) {
            issue(it + 1);
            asm volatile("cp.async.wait_group 1;" ::: "memory");
        } else {
            asm volatile("cp.async.wait_group 0;" ::: "memory");
        }
        __syncthreads();

        u32 base = smem0 + (it & 1) * 65536;
#pragma unroll
        for (int k16 = 0; k16 < 4; k16++) {
            int kg0 = k16 * 2;
            u32 ah[2][4], al[2][4];
#pragma unroll
            for (int mt = 0; mt < 2; mt++) {
                u32 off = swz((u32)((mBase + mt * 16 + aRowOf) * 128 + (kg0 + aKg) * 16));
                ldm4(ah[mt], base + off);
                ldm4(al[mt], base + 16384 + off);
            }
#pragma unroll
            for (int nt = 0; nt < 4; nt++) {
                u32 off = swz((u32)((nBase + nt * 16 + bRowOf) * 128 + (kg0 + bKg) * 16));
                u32 bh[4], bl[4];
                ldm4(bh, base + 32768 + off);
                ldm4(bl, base + 49152 + off);
#pragma unroll
                for (int mt = 0; mt < 2; mt++) {
                    mma16816(acc[mt][nt * 2],     ah[mt], &bh[0]);
                    mma16816(acc[mt][nt * 2],     al[mt], &bh[0]);
                    mma16816(acc[mt][nt * 2],     ah[mt], &bl[0]);
                    mma16816(acc[mt][nt * 2 + 1], ah[mt], &bh[2]);
                    mma16816(acc[mt][nt * 2 + 1], al[mt], &bh[2]);
                    mma16816(acc[mt][nt * 2 + 1], ah[mt], &bl[2]);
                }
            }
        }
        __syncthreads();
    }

    // ---------------- epilogue from register accumulators ----------------
    const float* bb = A.bias[head];
    int rQ = lane >> 2;               // row within m16 (0..7)
    int cQ = (lane & 3) * 2;          // col pair within n8

#pragma unroll
    for (int mt = 0; mt < 2; mt++) {
#pragma unroll
        for (int nt = 0; nt < 8; nt++) {
            int co0 = cb * 128 + nBase + nt * 8 + cQ;
#pragma unroll
            for (int half = 0; half < 2; half++) {
                int row = mBase + mt * 16 + rQ + half * 8;
                int pr = row >> 4, pc = row & 15;
                int y = y0 + pr, x = x0 + pc;
                if (x >= W) continue;
                float v0 = acc[mt][nt][half * 2];
                float v1 = acc[mt][nt][half * 2 + 1];
                if (MAIN) {
                    v0 = fmaxf(v0 + bb[co0], 0.f);
                    v1 = fmaxf(v1 + bb[co0 + 1], 0.f);
                    __nv_bfloat16 h0 = __float2bfloat16(v0);
                    __nv_bfloat16 h1 = __float2bfloat16(v1);
                    __nv_bfloat16 l0 = __float2bfloat16(v0 - __bfloat162float(h0));
                    __nv_bfloat16 l1 = __float2bfloat16(v1 - __bfloat162float(h1));
                    u32 hw = (u32)__bfloat16_as_ushort(h0) | ((u32)__bfloat16_as_ushort(h1) << 16);
                    u32 lw = (u32)__bfloat16_as_ushort(l0) | ((u32)__bfloat16_as_ushort(l1) << 16);
                    long long ob = (posBaseG + (long long)y * W + x) * 256 + co0;
                    *(u32*)(A.oHi[head] + ob) = hw;
                    *(u32*)(A.oLo[head] + ob) = lw;
                } else {
                    long long rowB = (long long)n * ANCH_TOT + posO9[s] + (long long)(y * W + x) * 9;
#pragma unroll
                    for (int e = 0; e < 2; e++) {
                        int co = co0 + e;
                        if (co < A.cOut) {
                            float v = (e ? v1 : v0) + bb[co];
                            int a = co / A.kk, c = co - a * A.kk;
                            A.outP[(rowB + a) * (long long)A.kk + c] = v;
                        }
                    }
                }
            }
        }
    }
}

// ---------------- host ----------------
extern "C" void kernel_launch(void* const* d_in, const int* in_sizes, int n_in,
                              void* d_out, int out_size)
{
    (void)in_sizes; (void)out_size;
    if (n_in < 13) return;

    const float* feat[5];
    for (int i = 0; i < 5; i++) feat[i] = (const float*)d_in[i];
    const float* cls_conv_w = (const float*)d_in[5];
    const float* cls_conv_b = (const float*)d_in[6];
    const float* cls_out_w  = (const float*)d_in[7];
    const float* cls_out_b  = (const float*)d_in[8];
    const float* reg_conv_w = (const float*)d_in[9];
    const float* reg_conv_b = (const float*)d_in[10];
    const float* reg_out_w  = (const float*)d_in[11];
    const float* reg_out_b  = (const float*)d_in[12];

    __nv_bfloat16 *fHi, *fLo, *wHi, *wLo;
    __nv_bfloat16 *aHiA, *aLoA, *aHiB, *aLoB;
    cudaGetSymbolAddress((void**)&fHi, g_fHi);
    cudaGetSymbolAddress((void**)&fLo, g_fLo);
    cudaGetSymbolAddress((void**)&wHi, g_wHi);
    cudaGetSymbolAddress((void**)&wLo, g_wLo);
    cudaGetSymbolAddress((void**)&aHiA, g_aHiA);
    cudaGetSymbolAddress((void**)&aLoA, g_aLoA);
    cudaGetSymbolAddress((void**)&aHiB, g_aHiB);
    cudaGetSymbolAddress((void**)&aLoB, g_aLoB);

    cudaFuncSetAttribute(conv_tc<1>, cudaFuncAttributeMaxDynamicSharedMemorySize, 132096);
    cudaFuncSetAttribute(conv_tc<0>, cudaFuncAttributeMaxDynamicSharedMemorySize, 132096);

    const long long PL = 11173888LL;     // plane elems per head
    const long long WTRUNK = 589824LL;   // 9*256*256

    // prologues (2 launches total)
    split_f_k<<<4096, 256>>>(feat[0], feat[1], feat[2], feat[3], feat[4], fHi, fLo);
    {
        WAll wa{};
        for (int l = 0; l < 4; l++) {
            wa.r[l]     = { cls_conv_w + l * 589824, wHi + l * WTRUNK,       wLo + l * WTRUNK,       256 };
            wa.r[4 + l] = { reg_conv_w + l * 589824, wHi + (4 + l) * WTRUNK, wLo + (4 + l) * WTRUNK, 256 };
        }
        wa.r[8] = { cls_out_w, wHi + 4718592, wLo + 4718592, 819 };
        wa.r[9] = { reg_out_w, wHi + 6605568, wLo + 6605568, 36 };
        split_w_all<<<dim3(256, 10), 256>>>(wa);
    }

    // trunk layers
    __nv_bfloat16 *srcHi = fHi, *srcLo = fLo;      // layer0: feats (head-shared)
    bool srcIsFeat = true;
    __nv_bfloat16 *pHi[2] = {aHiA, aHiB}, *pLo[2] = {aLoA, aLoB};
    int dstIdx = 0;
    for (int l = 0; l < 4; l++) {
        CArgs a{};
        for (int h = 0; h < 2; h++) {
            a.aHi[h] = srcIsFeat ? srcHi : srcHi + h * PL;
            a.aLo[h] = srcIsFeat ? srcLo : srcLo + h * PL;
            a.wHi[h] = wHi + (h * 4 + l) * WTRUNK;
            a.wLo[h] = wLo + (h * 4 + l) * WTRUNK;
            a.bias[h] = (h == 0 ? cls_conv_b : reg_conv_b) + l * 256;
            a.oHi[h] = pHi[dstIdx] + h * PL;
            a.oLo[h] = pLo[dstIdx] + h * PL;
        }
        a.cOut = 256; a.kk = 1;
        conv_tc<1><<<dim3(171, 2, 4), THREADS, 132096>>>(a);
        srcHi = pHi[dstIdx]; srcLo = pLo[dstIdx];
        srcIsFeat = false;
        dstIdx ^= 1;
    }

    // cls output conv (head0 trunk result)
    {
        CArgs a{};
        a.aHi[0] = srcHi; a.aLo[0] = srcLo;
        a.wHi[0] = wHi + 4718592; a.wLo[0] = wLo + 4718592;
        a.bias[0] = cls_out_b;
        a.outP = (float*)d_out;
        a.cOut = 819; a.kk = 91;
        conv_tc<0><<<dim3(171, 7, 2), THREADS, 132096>>>(a);
    }
    // reg output conv (head1 trunk result)
    {
        CArgs a{};
        a.aHi[0] = srcHi + PL; a.aLo[0] = srcLo + PL;
        a.wHi[0] = wHi + 6605568; a.wLo[0] = wLo + 6605568;
        a.bias[0] = reg_out_b;
        a.outP = (float*)d_out + 35747712LL;   // 2 * 196416 * 91
        a.cOut = 36; a.kk = 4;
        conv_tc<0><<<dim3(171, 1, 2), THREADS, 132096>>>(a);
    }
}

// round 13
// speedup vs baseline: 1.3756x; 1.1448x over previous
#include <cuda_runtime.h>
#include <cuda_bf16.h>
#include <cstdint>

typedef unsigned int u32;
typedef unsigned long long u64;

#define THREADS 512
#define POS_TOT 21824
#define ANCH_TOT 196416LL

// ---------------- device scratch (no allocs) ----------------
__device__ __align__(256) __nv_bfloat16 g_fHi[11173888], g_fLo[11173888];
__device__ __align__(256) __nv_bfloat16 g_aHiA[2][11173888], g_aLoA[2][11173888];
__device__ __align__(256) __nv_bfloat16 g_aHiB[2][11173888], g_aLoB[2][11173888];
__device__ __align__(256) __nv_bfloat16 g_wHi[6688512], g_wLo[6688512];

// ---------------- helpers ----------------
__device__ __forceinline__ u32 smem_u32(const void* p) {
    u32 a; asm("{ .reg .u64 t; cvta.to.shared.u64 t, %1; cvt.u32.u64 %0, t; }" : "=r"(a) : "l"(p));
    return a;
}
__device__ __forceinline__ void cp16(u32 saddr, const void* g, bool pred) {
    int sz = pred ? 16 : 0;
    asm volatile("cp.async.cg.shared.global [%0], [%1], 16, %2;"
                 :: "r"(saddr), "l"(g), "r"(sz) : "memory");
}
__device__ __forceinline__ u32 swz(u32 off) { return off ^ ((off >> 3) & 0x70); }

// volatile (no CSE across buffer reuse) but NO memory clobber: ordering vs
// cp.async is provided by __syncthreads(); this frees ptxas to schedule.
__device__ __forceinline__ void ldm4(u32* r, u32 addr) {
    asm volatile("ldmatrix.sync.aligned.m8n8.x4.shared.b16 {%0,%1,%2,%3}, [%4];"
                 : "=r"(r[0]), "=r"(r[1]), "=r"(r[2]), "=r"(r[3]) : "r"(addr));
}
// NON-volatile: pure register computation; ptxas may interleave with ldmatrix.
__device__ __forceinline__ void mma16816(float* c, const u32* a, const u32* b) {
    asm("mma.sync.aligned.m16n8k16.row.col.f32.bf16.bf16.f32 "
        "{%0,%1,%2,%3}, {%4,%5,%6,%7}, {%8,%9}, {%0,%1,%2,%3};"
        : "+f"(c[0]), "+f"(c[1]), "+f"(c[2]), "+f"(c[3])
        : "r"(a[0]), "r"(a[1]), "r"(a[2]), "r"(a[3]), "r"(b[0]), "r"(b[1]));
}

// ---------------- prologue: split ALL weights in one launch ----------------
struct WRegion { const float* src; __nv_bfloat16* hi; __nv_bfloat16* lo; int Co; };
struct WAll { WRegion r[10]; };

__global__ void split_w_all(WAll wa) {
    WRegion rg = wa.r[blockIdx.y];
    int total = 9 * rg.Co * 256;
    for (int i = blockIdx.x * blockDim.x + threadIdx.x; i < total; i += gridDim.x * blockDim.x) {
        int tap = i / (rg.Co * 256);
        int rem = i - tap * (rg.Co * 256);
        int co = rem >> 8, ci = rem & 255;
        float v = rg.src[(co * 256 + ci) * 9 + tap];
        __nv_bfloat16 h = __float2bfloat16(v);
        __nv_bfloat16 l = __float2bfloat16(v - __bfloat162float(h));
        rg.hi[i] = h; rg.lo[i] = l;
    }
}

// ---------------- prologue: split feats NCHW -> [n][pos][ci] ----------------
__global__ void split_f_k(const float* f0, const float* f1, const float* f2,
                          const float* f3, const float* f4,
                          __nv_bfloat16* hi, __nv_bfloat16* lo) {
    const int pb[6] = {0, 16384, 20480, 21504, 21760, 21824};
    const int Hs[5] = {128, 64, 32, 16, 8};
    const float* fp[5] = {f0, f1, f2, f3, f4};
    long long total = 2LL * POS_TOT * 256;
    for (long long i = (long long)blockIdx.x * blockDim.x + threadIdx.x; i < total;
         i += (long long)gridDim.x * blockDim.x) {
        int n = (int)(i / (POS_TOT * 256LL));
        int r = (int)(i - (long long)n * POS_TOT * 256);
        int pos = r >> 8, ci = r & 255;
        int s = 0;
        for (int k = 1; k < 5; k++) if (pos >= pb[k]) s = k;
        int p = pos - pb[s];
        int HW = Hs[s] * Hs[s];
        float v = fp[s][((long long)n * 256 + ci) * HW + p];
        __nv_bfloat16 h = __float2bfloat16(v);
        __nv_bfloat16 l = __float2bfloat16(v - __bfloat162float(h));
        hi[i] = h; lo[i] = l;
    }
}

// ---------------- main tensor-core conv (warp mma.sync) ----------------
struct CArgs {
    const __nv_bfloat16 *aHi[2], *aLo[2];   // per-head act planes (base, n=0)
    const __nv_bfloat16 *wHi[2], *wLo[2];   // per-head weight region [tap][co][ci]
    const float* bias[2];
    __nv_bfloat16 *oHi[2], *oLo[2];         // MAIN output planes
    float* outP;                            // OUT output
    int cOut, kk;
};

// Block: M=128 pos (8x16 spatial tile) x N=128 co. 16 warps (4m x 4n), each 32M x 32N.
// 36 stages (9 taps x 4 ci-chunks of 64), 64KB/stage double buffered.
template<int MAIN>
__global__ __launch_bounds__(THREADS, 1) void conv_tc(CArgs A)
{
    extern __shared__ __align__(16) char dsm_raw[];

    const int tid = threadIdx.x, wid = tid >> 5, lane = tid & 31;

    const int Hs[5]  = {128, 64, 32, 16, 8};
    const int tXs[5] = {8, 4, 2, 1, 1};
    const int tSt[5] = {0, 128, 160, 168, 170};
    const int posG[5] = {0, 16384, 20480, 21504, 21760};
    const long long posO9[5] = {0, 147456, 184320, 193536, 195840};

    int bt = blockIdx.x;
    int s = 0;
#pragma unroll
    for (int i = 1; i < 5; i++) if (bt >= tSt[i]) s = i;
    int local = bt - tSt[s];
    int H = Hs[s], W = H, tX = tXs[s];
    int y0 = (local / tX) * 8, x0 = (local % tX) * 16;
    int cb = blockIdx.y;
    int z  = blockIdx.z;
    int head = MAIN ? (z >> 1) : 0;
    int n    = MAIN ? (z & 1)  : z;

    const __nv_bfloat16* aHi = A.aHi[head];
    const __nv_bfloat16* aLo = A.aLo[head];
    const __nv_bfloat16* wHi = A.wHi[head];
    const __nv_bfloat16* wLo = A.wLo[head];

    u32 smem0 = (smem_u32(dsm_raw) + 1023u) & ~1023u;

    long long posBaseG = (long long)n * POS_TOT + posG[s];

    // per-thread staging geometry (2 chunks of 16B per 16KB plane, 512 threads)
    int pr_[2], pc_[2], co_[2], c16e_[2];
    u32 swo_[2];
    bool okB_[2];
#pragma unroll
    for (int q = 0; q < 2; q++) {
        int ch = tid * 2 + q;            // 0..1023
        int row = ch >> 3, c16 = ch & 7;
        pr_[q] = row >> 4; pc_[q] = row & 15;
        c16e_[q] = c16 * 8;
        swo_[q] = swz((u32)(row * 128 + c16 * 16));
        co_[q] = cb * 128 + row;
        okB_[q] = co_[q] < A.cOut;
    }

    auto issue = [&](int it) {
        int buf = it & 1;
        int tap = it >> 2, kcq = it & 3;
        int dy = tap / 3 - 1, dx = tap % 3 - 1;
        int cic = kcq * 64;
        u32 base = smem0 + buf * 65536;
        long long wStageBase = ((long long)tap * A.cOut) * 256 + cic;
#pragma unroll
        for (int q = 0; q < 2; q++) {
            int gy = y0 + pr_[q] + dy, gx = x0 + pc_[q] + dx;
            bool ok = ((unsigned)gy < (unsigned)H) && ((unsigned)gx < (unsigned)W);
            long long e = (posBaseG + (long long)gy * W + gx) * 256 + cic + c16e_[q];
            cp16(base + swo_[q],         aHi + e, ok);
            cp16(base + 16384 + swo_[q], aLo + e, ok);
            long long ew = wStageBase + (long long)co_[q] * 256 + c16e_[q];
            cp16(base + 32768 + swo_[q], wHi + ew, okB_[q]);
            cp16(base + 49152 + swo_[q], wLo + ew, okB_[q]);
        }
        asm volatile("cp.async.commit_group;" ::: "memory");
    };

    // warp tile: 32M x 32N (4m x 4n warp grid)
    const int mBase = (wid & 3) * 32;
    const int nBase = (wid >> 2) * 32;
    // ldmatrix lane-derived offsets
    const int aTile  = lane >> 3;
    const int aRowOf = ((aTile & 1) << 3) + (lane & 7);
    const int aKg    = aTile >> 1;
    const int bRowOf = (((lane >> 4) & 1) << 3) + (lane & 7);
    const int bKg    = (lane >> 3) & 1;

    float acc[2][4][4];
#pragma unroll
    for (int mt = 0; mt < 2; mt++)
#pragma unroll
        for (int nt = 0; nt < 4; nt++)
#pragma unroll
            for (int j = 0; j < 4; j++) acc[mt][nt][j] = 0.f;

    issue(0);

    for (int it = 0; it < 36; ++it) {
        if (it < 35) {
            issue(it + 1);
            asm volatile("cp.async.wait_group 1;" ::: "memory");
        } else {
            asm volatile("cp.async.wait_group 0;" ::: "memory");
        }
        __syncthreads();

        u32 base = smem0 + (it & 1) * 65536;
#pragma unroll
        for (int k16 = 0; k16 < 4; k16++) {
            int kg0 = k16 * 2;
            u32 ah[2][4], al[2][4];
#pragma unroll
            for (int mt = 0; mt < 2; mt++) {
                u32 off = swz((u32)((mBase + mt * 16 + aRowOf) * 128 + (kg0 + aKg) * 16));
                ldm4(ah[mt], base + off);
                ldm4(al[mt], base + 16384 + off);
            }
#pragma unroll
            for (int nt = 0; nt < 2; nt++) {
                u32 off = swz((u32)((nBase + nt * 16 + bRowOf) * 128 + (kg0 + bKg) * 16));
                u32 bh[4], bl[4];
                ldm4(bh, base + 32768 + off);
                ldm4(bl, base + 49152 + off);
#pragma unroll
                for (int mt = 0; mt < 2; mt++) {
                    mma16816(acc[mt][nt * 2],     ah[mt], &bh[0]);
                    mma16816(acc[mt][nt * 2],     al[mt], &bh[0]);
                    mma16816(acc[mt][nt * 2],     ah[mt], &bl[0]);
                    mma16816(acc[mt][nt * 2 + 1], ah[mt], &bh[2]);
                    mma16816(acc[mt][nt * 2 + 1], al[mt], &bh[2]);
                    mma16816(acc[mt][nt * 2 + 1], ah[mt], &bl[2]);
                }
            }
        }
        __syncthreads();
    }

    // ---------------- epilogue from register accumulators ----------------
    const float* bb = A.bias[head];
    int rQ = lane >> 2;               // row within m16 (0..7)
    int cQ = (lane & 3) * 2;          // col pair within n8

#pragma unroll
    for (int mt = 0; mt < 2; mt++) {
#pragma unroll
        for (int nt = 0; nt < 4; nt++) {
            int co0 = cb * 128 + nBase + nt * 8 + cQ;
#pragma unroll
            for (int half = 0; half < 2; half++) {
                int row = mBase + mt * 16 + rQ + half * 8;
                int pr = row >> 4, pc = row & 15;
                int y = y0 + pr, x = x0 + pc;
                if (x >= W) continue;
                float v0 = acc[mt][nt][half * 2];
                float v1 = acc[mt][nt][half * 2 + 1];
                if (MAIN) {
                    v0 = fmaxf(v0 + bb[co0], 0.f);
                    v1 = fmaxf(v1 + bb[co0 + 1], 0.f);
                    __nv_bfloat16 h0 = __float2bfloat16(v0);
                    __nv_bfloat16 h1 = __float2bfloat16(v1);
                    __nv_bfloat16 l0 = __float2bfloat16(v0 - __bfloat162float(h0));
                    __nv_bfloat16 l1 = __float2bfloat16(v1 - __bfloat162float(h1));
                    u32 hw = (u32)__bfloat16_as_ushort(h0) | ((u32)__bfloat16_as_ushort(h1) << 16);
                    u32 lw = (u32)__bfloat16_as_ushort(l0) | ((u32)__bfloat16_as_ushort(l1) << 16);
                    long long ob = (posBaseG + (long long)y * W + x) * 256 + co0;
                    *(u32*)(A.oHi[head] + ob) = hw;
                    *(u32*)(A.oLo[head] + ob) = lw;
                } else {
                    long long rowB = (long long)n * ANCH_TOT + posO9[s] + (long long)(y * W + x) * 9;
#pragma unroll
                    for (int e = 0; e < 2; e++) {
                        int co = co0 + e;
                        if (co < A.cOut) {
                            float v = (e ? v1 : v0) + bb[co];
                            int a = co / A.kk, c = co - a * A.kk;
                            A.outP[(rowB + a) * (long long)A.kk + c] = v;
                        }
                    }
                }
            }
        }
    }
}

// ---------------- host ----------------
extern "C" void kernel_launch(void* const* d_in, const int* in_sizes, int n_in,
                              void* d_out, int out_size)
{
    (void)in_sizes; (void)out_size;
    if (n_in < 13) return;

    const float* feat[5];
    for (int i = 0; i < 5; i++) feat[i] = (const float*)d_in[i];
    const float* cls_conv_w = (const float*)d_in[5];
    const float* cls_conv_b = (const float*)d_in[6];
    const float* cls_out_w  = (const float*)d_in[7];
    const float* cls_out_b  = (const float*)d_in[8];
    const float* reg_conv_w = (const float*)d_in[9];
    const float* reg_conv_b = (const float*)d_in[10];
    const float* reg_out_w  = (const float*)d_in[11];
    const float* reg_out_b  = (const float*)d_in[12];

    __nv_bfloat16 *fHi, *fLo, *wHi, *wLo;
    __nv_bfloat16 *aHiA, *aLoA, *aHiB, *aLoB;
    cudaGetSymbolAddress((void**)&fHi, g_fHi);
    cudaGetSymbolAddress((void**)&fLo, g_fLo);
    cudaGetSymbolAddress((void**)&wHi, g_wHi);
    cudaGetSymbolAddress((void**)&wLo, g_wLo);
    cudaGetSymbolAddress((void**)&aHiA, g_aHiA);
    cudaGetSymbolAddress((void**)&aLoA, g_aLoA);
    cudaGetSymbolAddress((void**)&aHiB, g_aHiB);
    cudaGetSymbolAddress((void**)&aLoB, g_aLoB);

    cudaFuncSetAttribute(conv_tc<1>, cudaFuncAttributeMaxDynamicSharedMemorySize, 132096);
    cudaFuncSetAttribute(conv_tc<0>, cudaFuncAttributeMaxDynamicSharedMemorySize, 132096);

    const long long PL = 11173888LL;     // plane elems per head
    const long long WTRUNK = 589824LL;   // 9*256*256

    // prologues (2 launches total)
    split_f_k<<<4096, 256>>>(feat[0], feat[1], feat[2], feat[3], feat[4], fHi, fLo);
    {
        WAll wa{};
        for (int l = 0; l < 4; l++) {
            wa.r[l]     = { cls_conv_w + l * 589824, wHi + l * WTRUNK,       wLo + l * WTRUNK,       256 };
            wa.r[4 + l] = { reg_conv_w + l * 589824, wHi + (4 + l) * WTRUNK, wLo + (4 + l) * WTRUNK, 256 };
        }
        wa.r[8] = { cls_out_w, wHi + 4718592, wLo + 4718592, 819 };
        wa.r[9] = { reg_out_w, wHi + 6605568, wLo + 6605568, 36 };
        split_w_all<<<dim3(256, 10), 256>>>(wa);
    }

    // trunk layers
    __nv_bfloat16 *srcHi = fHi, *srcLo = fLo;      // layer0: feats (head-shared)
    bool srcIsFeat = true;
    __nv_bfloat16 *pHi[2] = {aHiA, aHiB}, *pLo[2] = {aLoA, aLoB};
    int dstIdx = 0;
    for (int l = 0; l < 4; l++) {
        CArgs a{};
        for (int h = 0; h < 2; h++) {
            a.aHi[h] = srcIsFeat ? srcHi : srcHi + h * PL;
            a.aLo[h] = srcIsFeat ? srcLo : srcLo + h * PL;
            a.wHi[h] = wHi + (h * 4 + l) * WTRUNK;
            a.wLo[h] = wLo + (h * 4 + l) * WTRUNK;
            a.bias[h] = (h == 0 ? cls_conv_b : reg_conv_b) + l * 256;
            a.oHi[h] = pHi[dstIdx] + h * PL;
            a.oLo[h] = pLo[dstIdx] + h * PL;
        }
        a.cOut = 256; a.kk = 1;
        conv_tc<1><<<dim3(171, 2, 4), THREADS, 132096>>>(a);
        srcHi = pHi[dstIdx]; srcLo = pLo[dstIdx];
        srcIsFeat = false;
        dstIdx ^= 1;
    }

    // cls output conv (head0 trunk result)
    {
        CArgs a{};
        a.aHi[0] = srcHi; a.aLo[0] = srcLo;
        a.wHi[0] = wHi + 4718592; a.wLo[0] = wLo + 4718592;
        a.bias[0] = cls_out_b;
        a.outP = (float*)d_out;
        a.cOut = 819; a.kk = 91;
        conv_tc<0><<<dim3(171, 7, 2), THREADS, 132096>>>(a);
    }
    // reg output conv (head1 trunk result)
    {
        CArgs a{};
        a.aHi[0] = srcHi + PL; a.aLo[0] = srcLo + PL;
        a.wHi[0] = wHi + 6605568; a.wLo[0] = wLo + 6605568;
        a.bias[0] = reg_out_b;
        a.outP = (float*)d_out + 35747712LL;   // 2 * 196416 * 91
        a.cOut = 36; a.kk = 4;
        conv_tc<0><<<dim3(171, 1, 2), THREADS, 132096>>>(a);
    }
}